// round 3
// baseline (speedup 1.0000x reference)
#include <cuda_runtime.h>
#include <math.h>

#define NUM_NODES   8192
#define MEME_DIM    64
#define VISION      2048
#define K_IN        32
#define VOCAB_N     256
#define G_TOT       (NUM_NODES * MEME_DIM)
#define TILE_FLOATS (MEME_DIM * VOCAB_N)   // 16384 floats = 64KB

// Scratch (device globals; no allocation allowed)
__device__ float  d_g_raw[G_TOT];
__device__ float2 d_partials[NUM_NODES];
__device__ float  d_stats[2];  // [0]=mean, [1]=inv_std

// ---------------------------------------------------------------------------
// Kernel 1: per-node gather + mean over K=32 inputs; per-block sum/sumsq partials
// ---------------------------------------------------------------------------
__global__ __launch_bounds__(256) void gather_kernel(
    const float* __restrict__ x,          // [2048, 64]
    const float* __restrict__ memes,      // [8192, 64]
    const int*   __restrict__ idx)        // [8192, 32]
{
    const int n   = blockIdx.x;
    const int tid = threadIdx.x;
    const int e   = tid & 63;
    const int kb  = tid >> 6;   // 0..3

    const int* row_idx = idx + n * K_IN;

    float acc = 0.f;
#pragma unroll
    for (int j = 0; j < 8; j++) {
        int r = __ldg(row_idx + kb + 4 * j);
        const float* src = (r < VISION) ? (x + (size_t)r * MEME_DIM)
                                        : (memes + (size_t)(r - VISION) * MEME_DIM);
        acc += __ldg(src + e);
    }

    __shared__ float red[256];
    red[tid] = acc;
    __syncthreads();

    float g = 0.f;
    if (tid < 64) {
        g = (red[tid] + red[tid + 64] + red[tid + 128] + red[tid + 192]) * (1.f / 32.f);
        d_g_raw[n * MEME_DIM + e] = g;
    }

    // block reduce sum & sumsq of the 64 g values (other threads contribute 0)
    float s = (tid < 64) ? g : 0.f;
    float q = s * s;
    const int lane = tid & 31, w = tid >> 5;
#pragma unroll
    for (int o = 16; o > 0; o >>= 1) {
        s += __shfl_down_sync(0xffffffffu, s, o);
        q += __shfl_down_sync(0xffffffffu, q, o);
    }
    __shared__ float ws[8], wq[8];
    if (lane == 0) { ws[w] = s; wq[w] = q; }
    __syncthreads();
    if (tid == 0) {
        float S = 0.f, Q = 0.f;
#pragma unroll
        for (int i = 0; i < 8; i++) { S += ws[i]; Q += wq[i]; }
        d_partials[n] = make_float2(S, Q);
    }
}

// ---------------------------------------------------------------------------
// Kernel 2: reduce partials -> global mean / inv_std (ddof=1), deterministic
// ---------------------------------------------------------------------------
__global__ __launch_bounds__(256) void stats_kernel()
{
    __shared__ double ssum[256], ssq[256];
    const int tid = threadIdx.x;
    double s = 0.0, q = 0.0;
    for (int i = tid; i < NUM_NODES; i += 256) {
        float2 p = d_partials[i];
        s += (double)p.x;
        q += (double)p.y;
    }
    ssum[tid] = s; ssq[tid] = q;
    __syncthreads();
    for (int st = 128; st > 0; st >>= 1) {
        if (tid < st) { ssum[tid] += ssum[tid + st]; ssq[tid] += ssq[tid + st]; }
        __syncthreads();
    }
    if (tid == 0) {
        const double N = (double)G_TOT;
        double mean = ssum[0] / N;
        double var  = (ssq[0] - ssum[0] * ssum[0] / N) / (N - 1.0);
        d_stats[0] = (float)mean;
        d_stats[1] = (float)(1.0 / sqrt(var));
    }
}

// ---------------------------------------------------------------------------
// Kernel 3: fused remix. One node per CTA. vocab[n] tile loaded into smem once.
// ---------------------------------------------------------------------------
__global__ __launch_bounds__(256) void remix_kernel(
    const float* __restrict__ vocab,       // [8192, 64, 256]
    const float* __restrict__ raw_sc,      // [1]
    const float* __restrict__ raw_sh,      // [1]
    float*       __restrict__ out)         // [8192, 64]
{
    extern __shared__ float smem[];
    float* vs = smem;                       // 16384 floats: vocab tile [64][256]
    float* gs = smem + TILE_FLOATS;         // 64 floats: standardized g row
    float* fs = gs + MEME_DIM;              // 256 floats: fractions

    const int n    = blockIdx.x;
    const int tid  = threadIdx.x;
    const int lane = tid & 31, w = tid >> 5;

    // standardized g row
    if (tid < MEME_DIM) {
        float mean = d_stats[0], istd = d_stats[1];
        gs[tid] = (d_g_raw[n * MEME_DIM + tid] - mean) * istd;
    }

    // load vocab tile (64KB), float4 coalesced
    {
        const float4* vsrc = (const float4*)(vocab + (size_t)n * TILE_FLOATS);
        float4* vdst = (float4*)vs;
#pragma unroll
        for (int i = 0; i < 16; i++)
            vdst[tid + 256 * i] = __ldg(vsrc + tid + 256 * i);
    }
    __syncthreads();

    // dot products: thread tid owns vocab column v = tid
    float acc = 0.f;
#pragma unroll
    for (int e = 0; e < MEME_DIM; e++)
        acc = fmaf(gs[e], vs[e * VOCAB_N + tid], acc);

    // block reduce sum & sumsq over 256 dot values
    __shared__ float wsum[8], wsq[8];
    {
        float s = acc, q = acc * acc;
#pragma unroll
        for (int o = 16; o > 0; o >>= 1) {
            s += __shfl_down_sync(0xffffffffu, s, o);
            q += __shfl_down_sync(0xffffffffu, q, o);
        }
        if (lane == 0) { wsum[w] = s; wsq[w] = q; }
    }
    __syncthreads();
    float bsum = 0.f, bsq = 0.f;
#pragma unroll
    for (int i = 0; i < 8; i++) { bsum += wsum[i]; bsq += wsq[i]; }

    const float m   = bsum * (1.f / 256.f);
    float var = (bsq - bsum * bsum * (1.f / 256.f)) * (1.f / 255.f);
    var = fmaxf(var, 0.f);
    const float sd  = sqrtf(var) + 0.001f;

    const float sc   = expf(__ldg(raw_sc));   // soft_clip
    const float lnsh = __ldg(raw_sh);         // ln(sharpness) == raw_sharpness

    float d = (acc - m) / sd;
    d = tanhf(d / sc) * sc;
    float p = expf(d * lnsh);

    // block reduce sum of p
    __syncthreads();  // protect wsum reuse
    {
        float s = p;
#pragma unroll
        for (int o = 16; o > 0; o >>= 1)
            s += __shfl_down_sync(0xffffffffu, s, o);
        if (lane == 0) wsum[w] = s;
    }
    __syncthreads();
    float psum = 0.f;
#pragma unroll
    for (int i = 0; i < 8; i++) psum += wsum[i];

    fs[tid] = p / (psum + 0.001f);
    __syncthreads();

    // output GEMV: warp w handles e rows {8w .. 8w+7}; lanes stride v, conflict-free
#pragma unroll
    for (int r = 0; r < 8; r++) {
        const int e = w * 8 + r;
        float a = 0.f;
#pragma unroll
        for (int c = 0; c < 8; c++) {
            const int v = lane + 32 * c;
            a = fmaf(vs[e * VOCAB_N + v], fs[v], a);
        }
#pragma unroll
        for (int o = 16; o > 0; o >>= 1)
            a += __shfl_down_sync(0xffffffffu, a, o);
        if (lane == 0) out[(size_t)n * MEME_DIM + e] = a;
    }
}

// ---------------------------------------------------------------------------
extern "C" void kernel_launch(void* const* d_in, const int* in_sizes, int n_in,
                              void* d_out, int out_size)
{
    const float* x      = (const float*)d_in[0];   // [2048, 64]
    const float* memes  = (const float*)d_in[1];   // [8192, 64]
    const int*   idx    = (const int*)  d_in[2];   // [8192, 32]
    const float* vocab  = (const float*)d_in[3];   // [8192, 64, 256]
    const float* raw_sc = (const float*)d_in[4];   // [1]
    const float* raw_sh = (const float*)d_in[5];   // [1]
    float* out = (float*)d_out;

    const int smem_bytes = (TILE_FLOATS + MEME_DIM + VOCAB_N) * sizeof(float); // 66816
    cudaFuncSetAttribute(remix_kernel, cudaFuncAttributeMaxDynamicSharedMemorySize, smem_bytes);

    gather_kernel<<<NUM_NODES, 256>>>(x, memes, idx);
    stats_kernel<<<1, 256>>>();
    remix_kernel<<<NUM_NODES, 256, smem_bytes>>>(vocab, raw_sc, raw_sh, out);
}

// round 4
// speedup vs baseline: 1.0860x; 1.0860x over previous
#include <cuda_runtime.h>
#include <math.h>

#define NUM_NODES   8192
#define MEME_DIM    64
#define VISION      2048
#define K_IN        32
#define VOCAB_N     256
#define G_TOT       (NUM_NODES * MEME_DIM)
#define TILE_FLOATS (MEME_DIM * VOCAB_N)        // 16384 floats
#define TILE_BYTES  (TILE_FLOATS * 4)           // 65536 bytes
#define GRID_P      148                          // persistent CTAs (1/SM)

// Scratch (device globals; no allocation allowed)
__device__ float  d_g_raw[G_TOT];
__device__ float2 d_partials[NUM_NODES];
__device__ float  d_stats[2];  // [0]=mean, [1]=inv_std

// ---------------------------------------------------------------------------
// PTX helpers
// ---------------------------------------------------------------------------
__device__ __forceinline__ unsigned smem_u32(const void* p) {
    unsigned r;
    asm("{ .reg .u64 t; cvta.to.shared.u64 t, %1; cvt.u32.u64 %0, t; }"
        : "=r"(r) : "l"(p));
    return r;
}

__device__ __forceinline__ void mbar_init(unsigned addr, unsigned count) {
    asm volatile("mbarrier.init.shared.b64 [%0], %1;" :: "r"(addr), "r"(count) : "memory");
}

__device__ __forceinline__ void mbar_expect_tx(unsigned addr, unsigned bytes) {
    asm volatile("mbarrier.arrive.expect_tx.shared.b64 _, [%0], %1;"
                 :: "r"(addr), "r"(bytes) : "memory");
}

__device__ __forceinline__ void bulk_ldgsts(unsigned dst_smem, const void* src_gmem,
                                            unsigned bytes, unsigned mbar) {
    asm volatile(
        "cp.async.bulk.shared::cta.global.mbarrier::complete_tx::bytes "
        "[%0], [%1], %2, [%3];"
        :: "r"(dst_smem), "l"(src_gmem), "r"(bytes), "r"(mbar) : "memory");
}

__device__ __forceinline__ void mbar_wait(unsigned addr, unsigned phase) {
    asm volatile(
        "{\n\t"
        ".reg .pred P;\n\t"
        "WAIT_%=:\n\t"
        "mbarrier.try_wait.parity.acquire.cta.shared::cta.b64 P, [%0], %1, 0x989680;\n\t"
        "@!P bra WAIT_%=;\n\t"
        "}"
        :: "r"(addr), "r"(phase) : "memory");
}

// ---------------------------------------------------------------------------
// Kernel 1: per-node gather + mean over K=32 inputs; per-block sum/sumsq partials
// Vectorized: thread (kb, f4) gathers float4 f4 of rows kb and kb+16.
// ---------------------------------------------------------------------------
__global__ __launch_bounds__(256) void gather_kernel(
    const float* __restrict__ x,          // [2048, 64]
    const float* __restrict__ memes,      // [8192, 64]
    const int*   __restrict__ idx)        // [8192, 32]
{
    const int n   = blockIdx.x;
    const int tid = threadIdx.x;
    const int f4  = tid & 15;   // float4 index within 64-float row
    const int kb  = tid >> 4;   // 0..15

    __shared__ int sidx[K_IN];
    if (tid < K_IN) sidx[tid] = __ldg(idx + n * K_IN + tid);
    __syncthreads();

    float4 acc = make_float4(0.f, 0.f, 0.f, 0.f);
#pragma unroll
    for (int j = 0; j < 2; j++) {
        int r = sidx[kb + 16 * j];
        const float4* src = (r < VISION)
            ? (const float4*)(x + (size_t)r * MEME_DIM)
            : (const float4*)(memes + (size_t)(r - VISION) * MEME_DIM);
        float4 v = __ldg(src + f4);
        acc.x += v.x; acc.y += v.y; acc.z += v.z; acc.w += v.w;
    }

    __shared__ float4 red[256];
    red[tid] = acc;
    __syncthreads();
    if (tid < 128) {
        float4 b = red[tid + 128];
        red[tid].x += b.x; red[tid].y += b.y; red[tid].z += b.z; red[tid].w += b.w;
    }
    __syncthreads();
    if (tid < 64) {
        float4 b = red[tid + 64];
        red[tid].x += b.x; red[tid].y += b.y; red[tid].z += b.z; red[tid].w += b.w;
    }
    __syncthreads();
    if (tid < 16) {
        float4 a = red[tid], b = red[tid + 16], c = red[tid + 32], d = red[tid + 48];
        float4 g;
        g.x = (a.x + b.x + c.x + d.x) * (1.f / 32.f);
        g.y = (a.y + b.y + c.y + d.y) * (1.f / 32.f);
        g.z = (a.z + b.z + c.z + d.z) * (1.f / 32.f);
        g.w = (a.w + b.w + c.w + d.w) * (1.f / 32.f);
        ((float4*)(d_g_raw + (size_t)n * MEME_DIM))[tid] = g;

        float s = g.x + g.y + g.z + g.w;
        float q = g.x * g.x + g.y * g.y + g.z * g.z + g.w * g.w;
#pragma unroll
        for (int o = 8; o > 0; o >>= 1) {
            s += __shfl_down_sync(0xffffu, s, o, 16);
            q += __shfl_down_sync(0xffffu, q, o, 16);
        }
        if (tid == 0) d_partials[n] = make_float2(s, q);
    }
}

// ---------------------------------------------------------------------------
// Kernel 2: reduce partials -> global mean / inv_std (ddof=1), deterministic
// ---------------------------------------------------------------------------
__global__ __launch_bounds__(256) void stats_kernel()
{
    __shared__ double ssum[256], ssq[256];
    const int tid = threadIdx.x;
    double s = 0.0, q = 0.0;
    for (int i = tid; i < NUM_NODES; i += 256) {
        float2 p = d_partials[i];
        s += (double)p.x;
        q += (double)p.y;
    }
    ssum[tid] = s; ssq[tid] = q;
    __syncthreads();
    for (int st = 128; st > 0; st >>= 1) {
        if (tid < st) { ssum[tid] += ssum[tid + st]; ssq[tid] += ssq[tid + st]; }
        __syncthreads();
    }
    if (tid == 0) {
        const double N = (double)G_TOT;
        double mean = ssum[0] / N;
        double var  = (ssq[0] - ssum[0] * ssum[0] / N) / (N - 1.0);
        d_stats[0] = (float)mean;
        d_stats[1] = (float)(1.0 / sqrt(var));
    }
}

// ---------------------------------------------------------------------------
// Kernel 3: fused remix, persistent CTAs, TMA bulk-copy double buffered.
// One CTA per SM; each CTA streams ~55 vocab tiles; loads overlap compute.
// ---------------------------------------------------------------------------
__global__ __launch_bounds__(256, 1) void remix_kernel(
    const float* __restrict__ vocab,       // [8192, 64, 256]
    const float* __restrict__ raw_sc,      // [1]
    const float* __restrict__ raw_sh,      // [1]
    float*       __restrict__ out)         // [8192, 64]
{
    extern __shared__ __align__(128) float smem[];
    float* buf0 = smem;
    float* buf1 = smem + TILE_FLOATS;
    float* gs   = smem + 2 * TILE_FLOATS;     // 64 floats
    float* fs   = gs + MEME_DIM;              // 256 floats
    __shared__ __align__(8) unsigned long long mbar_s[2];
    __shared__ float wsum[8], wsq[8];

    const int tid  = threadIdx.x;
    const int lane = tid & 31, w = tid >> 5;

    const unsigned mb0 = smem_u32(&mbar_s[0]);
    const unsigned mb1 = smem_u32(&mbar_s[1]);
    const unsigned sb0 = smem_u32(buf0);
    const unsigned sb1 = smem_u32(buf1);

    if (tid == 0) {
        mbar_init(mb0, 1);
        mbar_init(mb1, 1);
        asm volatile("fence.proxy.async.shared::cta;" ::: "memory");
    }
    __syncthreads();

    const float sc   = expf(__ldg(raw_sc));
    const float lnsh = __ldg(raw_sh);
    const float mean = d_stats[0], istd = d_stats[1];

    const int n0 = blockIdx.x;
    if (tid == 0) {
        mbar_expect_tx(mb0, TILE_BYTES);
        bulk_ldgsts(sb0, vocab + (size_t)n0 * TILE_FLOATS, TILE_BYTES, mb0);
    }

    int it = 0;
    for (int n = n0; n < NUM_NODES; n += GRID_P, ++it) {
        const int b = it & 1;
        float* vs = b ? buf1 : buf0;

        // standardized g row for this node
        if (tid < MEME_DIM)
            gs[tid] = (d_g_raw[(size_t)n * MEME_DIM + tid] - mean) * istd;

        // prefetch next tile into the other buffer (safe: last read of that
        // buffer was fenced by the __syncthreads at the end of iter it-1)
        const int nn = n + GRID_P;
        if (nn < NUM_NODES && tid == 0) {
            const unsigned mbn = b ? mb0 : mb1;
            const unsigned sbn = b ? sb0 : sb1;
            mbar_expect_tx(mbn, TILE_BYTES);
            bulk_ldgsts(sbn, vocab + (size_t)nn * TILE_FLOATS, TILE_BYTES, mbn);
        }
        __syncthreads();                       // publish gs
        mbar_wait(b ? mb1 : mb0, (it >> 1) & 1);

        // ---- dot products: thread tid owns vocab column v = tid ----
        float acc = 0.f;
#pragma unroll
        for (int e = 0; e < MEME_DIM; e++)
            acc = fmaf(gs[e], vs[e * VOCAB_N + tid], acc);

        // block reduce sum & sumsq over 256 dot values
        {
            float s = acc, q = acc * acc;
#pragma unroll
            for (int o = 16; o > 0; o >>= 1) {
                s += __shfl_down_sync(0xffffffffu, s, o);
                q += __shfl_down_sync(0xffffffffu, q, o);
            }
            if (lane == 0) { wsum[w] = s; wsq[w] = q; }
        }
        __syncthreads();
        float bsum = 0.f, bsq = 0.f;
#pragma unroll
        for (int i = 0; i < 8; i++) { bsum += wsum[i]; bsq += wsq[i]; }

        const float m = bsum * (1.f / 256.f);
        float var = (bsq - bsum * bsum * (1.f / 256.f)) * (1.f / 255.f);
        var = fmaxf(var, 0.f);
        const float sd = sqrtf(var) + 0.001f;

        float d = (acc - m) / sd;
        d = tanhf(d / sc) * sc;
        float p = expf(d * lnsh);

        // block reduce sum of p
        __syncthreads();                       // protect wsum reuse
        {
            float s = p;
#pragma unroll
            for (int o = 16; o > 0; o >>= 1)
                s += __shfl_down_sync(0xffffffffu, s, o);
            if (lane == 0) wsum[w] = s;
        }
        __syncthreads();
        float psum = 0.f;
#pragma unroll
        for (int i = 0; i < 8; i++) psum += wsum[i];

        fs[tid] = p / (psum + 0.001f);
        __syncthreads();

        // ---- output GEMV: warp w -> e rows {8w..8w+7}; lanes stride v ----
#pragma unroll
        for (int r = 0; r < 8; r++) {
            const int e = w * 8 + r;
            float a = 0.f;
#pragma unroll
            for (int c = 0; c < 8; c++) {
                const int v = lane + 32 * c;
                a = fmaf(vs[e * VOCAB_N + v], fs[v], a);
            }
#pragma unroll
            for (int o = 16; o > 0; o >>= 1)
                a += __shfl_down_sync(0xffffffffu, a, o);
            if (lane == 0) out[(size_t)n * MEME_DIM + e] = a;
        }
        __syncthreads();                       // all reads of vs done
    }
}

// ---------------------------------------------------------------------------
extern "C" void kernel_launch(void* const* d_in, const int* in_sizes, int n_in,
                              void* d_out, int out_size)
{
    const float* x      = (const float*)d_in[0];   // [2048, 64]
    const float* memes  = (const float*)d_in[1];   // [8192, 64]
    const int*   idx    = (const int*)  d_in[2];   // [8192, 32]
    const float* vocab  = (const float*)d_in[3];   // [8192, 64, 256]
    const float* raw_sc = (const float*)d_in[4];   // [1]
    const float* raw_sh = (const float*)d_in[5];   // [1]
    float* out = (float*)d_out;

    const int smem_bytes = (2 * TILE_FLOATS + MEME_DIM + VOCAB_N) * sizeof(float); // 132352
    static int attr_set = 0;
    if (!attr_set) {
        cudaFuncSetAttribute(remix_kernel, cudaFuncAttributeMaxDynamicSharedMemorySize, smem_bytes);
        attr_set = 1;
    }

    gather_kernel<<<NUM_NODES, 256>>>(x, memes, idx);
    stats_kernel<<<1, 256>>>();
    remix_kernel<<<GRID_P, 256, smem_bytes>>>(vocab, raw_sc, raw_sh, out);
}

// round 6
// speedup vs baseline: 1.1330x; 1.0433x over previous
#include <cuda_runtime.h>
#include <math.h>

#define NUM_NODES   8192
#define MEME_DIM    64
#define VISION      2048
#define K_IN        32
#define VOCAB_N     256
#define G_TOT       (NUM_NODES * MEME_DIM)
#define TILE_FLOATS (MEME_DIM * VOCAB_N)        // 16384 floats
#define TILE_BYTES  (TILE_FLOATS * 4)           // 65536 bytes
#define GRID_P      148                          // persistent CTAs (1/SM)
#define RTHREADS    512

// Scratch (device globals; no allocation allowed)
__device__ float  d_g_raw[G_TOT];
__device__ float2 d_partials[NUM_NODES];
__device__ float  d_stats[2];  // [0]=mean, [1]=inv_std

// ---------------------------------------------------------------------------
// PTX helpers
// ---------------------------------------------------------------------------
__device__ __forceinline__ unsigned smem_u32(const void* p) {
    unsigned r;
    asm("{ .reg .u64 t; cvta.to.shared.u64 t, %1; cvt.u32.u64 %0, t; }"
        : "=r"(r) : "l"(p));
    return r;
}
__device__ __forceinline__ void mbar_init(unsigned addr, unsigned count) {
    asm volatile("mbarrier.init.shared.b64 [%0], %1;" :: "r"(addr), "r"(count) : "memory");
}
__device__ __forceinline__ void mbar_expect_tx(unsigned addr, unsigned bytes) {
    asm volatile("mbarrier.arrive.expect_tx.shared.b64 _, [%0], %1;"
                 :: "r"(addr), "r"(bytes) : "memory");
}
__device__ __forceinline__ void bulk_ldgsts(unsigned dst_smem, const void* src_gmem,
                                            unsigned bytes, unsigned mbar) {
    asm volatile(
        "cp.async.bulk.shared::cta.global.mbarrier::complete_tx::bytes "
        "[%0], [%1], %2, [%3];"
        :: "r"(dst_smem), "l"(src_gmem), "r"(bytes), "r"(mbar) : "memory");
}
__device__ __forceinline__ void mbar_wait(unsigned addr, unsigned phase) {
    asm volatile(
        "{\n\t"
        ".reg .pred P;\n\t"
        "WAIT_%=:\n\t"
        "mbarrier.try_wait.parity.acquire.cta.shared::cta.b64 P, [%0], %1, 0x989680;\n\t"
        "@!P bra WAIT_%=;\n\t"
        "}"
        :: "r"(addr), "r"(phase) : "memory");
}
__device__ __forceinline__ float fast_tanh(float x) {
    float r;
    asm("tanh.approx.f32 %0, %1;" : "=f"(r) : "f"(x));
    return r;
}

// ---------------------------------------------------------------------------
// Kernel 1: gather + mean. 2 nodes per 256-thread block; 4-way MLP per thread.
// ---------------------------------------------------------------------------
__global__ __launch_bounds__(256) void gather_kernel(
    const float* __restrict__ x,          // [2048, 64]
    const float* __restrict__ memes,      // [8192, 64]
    const int*   __restrict__ idx)        // [8192, 32]
{
    const int tid  = threadIdx.x;
    const int half = tid >> 7;            // 0/1 -> node within block
    const int t    = tid & 127;
    const int n    = blockIdx.x * 2 + half;
    const int f4   = t & 15;              // float4 slot in 64-float row
    const int kb   = t >> 4;              // 0..7

    const int* ri = idx + (size_t)n * K_IN;

    // 4 independent gathers per thread (k = kb, kb+8, kb+16, kb+24)
    float4 acc = make_float4(0.f, 0.f, 0.f, 0.f);
#pragma unroll
    for (int j = 0; j < 4; j++) {
        int r = __ldg(ri + kb + 8 * j);
        const float4* src = (r < VISION)
            ? (const float4*)(x + (size_t)r * MEME_DIM)
            : (const float4*)(memes + (size_t)(r - VISION) * MEME_DIM);
        float4 v = __ldg(src + f4);
        acc.x += v.x; acc.y += v.y; acc.z += v.z; acc.w += v.w;
    }

    __shared__ float4 red[256];
    red[tid] = acc;
    __syncthreads();
    if (t < 64) {
        float4 b = red[tid + 64];
        red[tid].x += b.x; red[tid].y += b.y; red[tid].z += b.z; red[tid].w += b.w;
    }
    __syncthreads();
    if (t < 32) {
        float4 b = red[tid + 32];
        red[tid].x += b.x; red[tid].y += b.y; red[tid].z += b.z; red[tid].w += b.w;
    }
    __syncthreads();
    if (t < 16) {
        float4 a = red[tid], b = red[tid + 16];
        float4 g;
        g.x = (a.x + b.x) * (1.f / 32.f);
        g.y = (a.y + b.y) * (1.f / 32.f);
        g.z = (a.z + b.z) * (1.f / 32.f);
        g.w = (a.w + b.w) * (1.f / 32.f);
        ((float4*)(d_g_raw + (size_t)n * MEME_DIM))[t] = g;

        float s = g.x + g.y + g.z + g.w;
        float q = g.x * g.x + g.y * g.y + g.z * g.z + g.w * g.w;
#pragma unroll
        for (int o = 8; o > 0; o >>= 1) {
            s += __shfl_down_sync(0xffffu, s, o, 16);
            q += __shfl_down_sync(0xffffu, q, o, 16);
        }
        if (t == 0) d_partials[n] = make_float2(s, q);
    }
}

// ---------------------------------------------------------------------------
// Kernel 2: reduce partials -> global mean / inv_std (ddof=1), deterministic
// ---------------------------------------------------------------------------
__global__ __launch_bounds__(256) void stats_kernel()
{
    __shared__ double ssum[256], ssq[256];
    const int tid = threadIdx.x;
    double s = 0.0, q = 0.0;
    for (int i = tid; i < NUM_NODES; i += 256) {
        float2 p = d_partials[i];
        s += (double)p.x;
        q += (double)p.y;
    }
    ssum[tid] = s; ssq[tid] = q;
    __syncthreads();
    for (int st = 128; st > 0; st >>= 1) {
        if (tid < st) { ssum[tid] += ssum[tid + st]; ssq[tid] += ssq[tid + st]; }
        __syncthreads();
    }
    if (tid == 0) {
        const double N = (double)G_TOT;
        double mean = ssum[0] / N;
        double var  = (ssq[0] - ssum[0] * ssum[0] / N) / (N - 1.0);
        d_stats[0] = (float)mean;
        d_stats[1] = (float)(1.0 / sqrt(var));
    }
}

// ---------------------------------------------------------------------------
// Kernel 3: fused remix. 512 threads, persistent, TMA double-buffered,
// all smem traffic via float4 (LDS.128), fast-math transcendentals.
// ---------------------------------------------------------------------------
__global__ __launch_bounds__(RTHREADS, 1) void remix_kernel(
    const float* __restrict__ vocab,       // [8192, 64, 256]
    const float* __restrict__ raw_sc,      // [1]
    const float* __restrict__ raw_sh,      // [1]
    float*       __restrict__ out)         // [8192, 64]
{
    extern __shared__ __align__(128) float smem[];
    float*  buf0 = smem;
    float*  buf1 = smem + TILE_FLOATS;
    float*  gs   = smem + 2 * TILE_FLOATS;          // 64 floats
    float4* fs4  = (float4*)(gs + MEME_DIM);        // 64 float4 (256 fractions)
    float4* pd4  = (float4*)(gs + MEME_DIM + VOCAB_N); // 512 float4 (8KB partials)
    __shared__ __align__(8) unsigned long long mbar_s[2];
    __shared__ float ws[2], wq[2], wp[2];

    const int tid  = threadIdx.x;
    const int lane = tid & 31, w = tid >> 5;
    const int c4   = tid & 63;     // float4 column group (4 cols)
    const int ch   = tid >> 6;     // e-chunk 0..7 (8 e's each)

    const unsigned mb0 = smem_u32(&mbar_s[0]);
    const unsigned mb1 = smem_u32(&mbar_s[1]);
    const unsigned sb0 = smem_u32(buf0);
    const unsigned sb1 = smem_u32(buf1);

    if (tid == 0) {
        mbar_init(mb0, 1);
        mbar_init(mb1, 1);
        asm volatile("fence.proxy.async.shared::cta;" ::: "memory");
    }
    __syncthreads();

    const float sc     = __expf(__ldg(raw_sc));
    const float inv_sc = __fdividef(1.f, sc);
    const float lnsh   = __ldg(raw_sh);
    const float mean   = d_stats[0], istd = d_stats[1];

    const int n0 = blockIdx.x;
    if (tid == 0) {
        mbar_expect_tx(mb0, TILE_BYTES);
        bulk_ldgsts(sb0, vocab + (size_t)n0 * TILE_FLOATS, TILE_BYTES, mb0);
    }

    int it = 0;
    for (int n = n0; n < NUM_NODES; n += GRID_P, ++it) {
        const int b = it & 1;
        const float4* vs4 = (const float4*)(b ? buf1 : buf0);

        // ---- phase A: gs + prefetch next tile into the other buffer ----
        if (tid < MEME_DIM)
            gs[tid] = (d_g_raw[(size_t)n * MEME_DIM + tid] - mean) * istd;
        const int nn = n + GRID_P;
        if (nn < NUM_NODES && tid == 0) {
            const unsigned mbn = b ? mb0 : mb1;
            const unsigned sbn = b ? sb0 : sb1;
            mbar_expect_tx(mbn, TILE_BYTES);
            bulk_ldgsts(sbn, vocab + (size_t)nn * TILE_FLOATS, TILE_BYTES, mbn);
        }
        __syncthreads();                                   // #1: publish gs
        mbar_wait(b ? mb1 : mb0, (it >> 1) & 1);

        // ---- phase B: dot-product partials (thread: 4 cols x 8 e's) ----
        {
            float4 a = make_float4(0.f, 0.f, 0.f, 0.f);
#pragma unroll
            for (int j = 0; j < 8; j++) {
                const int e = ch * 8 + j;
                const float4 vv = vs4[e * 64 + c4];
                const float ge = gs[e];
                a.x = fmaf(ge, vv.x, a.x);
                a.y = fmaf(ge, vv.y, a.y);
                a.z = fmaf(ge, vv.z, a.z);
                a.w = fmaf(ge, vv.w, a.w);
            }
            pd4[ch * 64 + c4] = a;
        }
        __syncthreads();                                   // #2

        // ---- phase C: combine partials (threads 0..63), row stats ----
        float4 dv = make_float4(0.f, 0.f, 0.f, 0.f);
        if (tid < 64) {
#pragma unroll
            for (int k = 0; k < 8; k++) {
                float4 p = pd4[k * 64 + tid];
                dv.x += p.x; dv.y += p.y; dv.z += p.z; dv.w += p.w;
            }
            float s = dv.x + dv.y + dv.z + dv.w;
            float q = dv.x * dv.x + dv.y * dv.y + dv.z * dv.z + dv.w * dv.w;
#pragma unroll
            for (int o = 16; o > 0; o >>= 1) {
                s += __shfl_down_sync(0xffffffffu, s, o);
                q += __shfl_down_sync(0xffffffffu, q, o);
            }
            if (lane == 0) { ws[w] = s; wq[w] = q; }
        }
        __syncthreads();                                   // #3

        // ---- phase D: nonlinearity + fractions (threads 0..63) ----
        float4 pv = make_float4(0.f, 0.f, 0.f, 0.f);
        if (tid < 64) {
            const float bsum = ws[0] + ws[1];
            const float bsq  = wq[0] + wq[1];
            const float m    = bsum * (1.f / 256.f);
            float var = (bsq - bsum * bsum * (1.f / 256.f)) * (1.f / 255.f);
            var = fmaxf(var, 0.f);
            const float inv_sd = __fdividef(1.f, sqrtf(var) + 0.001f);

            float4 d;
            d.x = (dv.x - m) * inv_sd; d.y = (dv.y - m) * inv_sd;
            d.z = (dv.z - m) * inv_sd; d.w = (dv.w - m) * inv_sd;
            d.x = fast_tanh(d.x * inv_sc) * sc; d.y = fast_tanh(d.y * inv_sc) * sc;
            d.z = fast_tanh(d.z * inv_sc) * sc; d.w = fast_tanh(d.w * inv_sc) * sc;
            pv.x = __expf(d.x * lnsh); pv.y = __expf(d.y * lnsh);
            pv.z = __expf(d.z * lnsh); pv.w = __expf(d.w * lnsh);

            float s = pv.x + pv.y + pv.z + pv.w;
#pragma unroll
            for (int o = 16; o > 0; o >>= 1)
                s += __shfl_down_sync(0xffffffffu, s, o);
            if (lane == 0) wp[w] = s;
        }
        __syncthreads();                                   // #4
        if (tid < 64) {
            const float inv_psum = __fdividef(1.f, wp[0] + wp[1] + 0.001f);
            float4 f;
            f.x = pv.x * inv_psum; f.y = pv.y * inv_psum;
            f.z = pv.z * inv_psum; f.w = pv.w * inv_psum;
            fs4[tid] = f;
        }
        __syncthreads();                                   // #5

        // ---- phase E: output GEMV. warp w -> rows 4w..4w+3.
        //      Each lane covers TWO float4 column groups: lane and lane+32. ----
        {
            const float4 f0 = fs4[lane];
            const float4 f1 = fs4[lane + 32];
#pragma unroll
            for (int r = 0; r < 4; r++) {
                const int e = w * 4 + r;
                const float4 v0 = vs4[e * 64 + lane];
                const float4 v1 = vs4[e * 64 + lane + 32];
                float a = v0.x * f0.x + v0.y * f0.y + v0.z * f0.z + v0.w * f0.w;
                a = fmaf(v1.x, f1.x, a);
                a = fmaf(v1.y, f1.y, a);
                a = fmaf(v1.z, f1.z, a);
                a = fmaf(v1.w, f1.w, a);
#pragma unroll
                for (int o = 16; o > 0; o >>= 1)
                    a += __shfl_down_sync(0xffffffffu, a, o);
                if (lane == 0) out[(size_t)n * MEME_DIM + e] = a;
            }
        }
        __syncthreads();                                   // #6: vs reads done
    }
}

// ---------------------------------------------------------------------------
extern "C" void kernel_launch(void* const* d_in, const int* in_sizes, int n_in,
                              void* d_out, int out_size)
{
    const float* x      = (const float*)d_in[0];   // [2048, 64]
    const float* memes  = (const float*)d_in[1];   // [8192, 64]
    const int*   idx    = (const int*)  d_in[2];   // [8192, 32]
    const float* vocab  = (const float*)d_in[3];   // [8192, 64, 256]
    const float* raw_sc = (const float*)d_in[4];   // [1]
    const float* raw_sh = (const float*)d_in[5];   // [1]
    float* out = (float*)d_out;

    const int smem_bytes =
        (2 * TILE_FLOATS + MEME_DIM + VOCAB_N + 4 * 512) * sizeof(float); // 140544
    static int attr_set = 0;
    if (!attr_set) {
        cudaFuncSetAttribute(remix_kernel, cudaFuncAttributeMaxDynamicSharedMemorySize, smem_bytes);
        attr_set = 1;
    }

    gather_kernel<<<NUM_NODES / 2, 256>>>(x, memes, idx);
    stats_kernel<<<1, 256>>>();
    remix_kernel<<<GRID_P, RTHREADS, smem_bytes>>>(vocab, raw_sc, raw_sh, out);
}